// round 1
// baseline (speedup 1.0000x reference)
#include <cuda_runtime.h>
#include <math.h>

// Problem constants
// B=16, P=1000, N=1000, E=256, H=16, D=16, HD=256
#define BSZ   16
#define PN    1000
#define NN    1000
#define ED    256
#define MROWS (BSZ * PN)   // 16000

// ---------------- scratch (no allocations allowed) ----------------
__device__ float g_K[MROWS * ED];
__device__ float g_V[MROWS * ED];
__device__ float g_Q[MROWS * ED];
__device__ float g_ATT[MROWS * ED];
__device__ float g_MH[MROWS * ED];
__device__ float g_ROWSUM[MROWS];

// ---------------- zero rowsums ----------------
__global__ void zero_k() {
    int i = blockIdx.x * 256 + threadIdx.x;
    if (i < MROWS) g_ROWSUM[i] = 0.f;
}

// ---------------- generic 128x128x(K=256) fp32 GEMM ----------------
// MODE 0: C = A @ B            (A [M,256] rowmajor, B [256,256] rowmajor, NN)
// MODE 1: C = A @ B + attr[row]*Wq_last_row[col]   (q projection w/ concat)
// MODE 2: C = A @ B + bias[col]                     (Wc + bc)
// MODE 3: per-batch (blockIdx.z) C = A @ B^T, epilogue:
//         e = exp(10*tanh(x/16) + mask), store e, rowsum += e
template <int MODE>
__global__ void __launch_bounds__(256)
gemm_k(const float* __restrict__ A, const float* __restrict__ Bm,
       float* __restrict__ C, int M, int N,
       const float* __restrict__ e1, const float* __restrict__ e2,
       float* __restrict__ rsum)
{
    __shared__ float As[16 * 132];
    __shared__ float Bs[16 * 132];

    const int tid = threadIdx.x;
    const int tx = tid & 15;
    const int ty = tid >> 4;
    const int m0 = blockIdx.y * 128;
    const int n0 = blockIdx.x * 128;

    if (MODE == 3) {
        const int z = blockIdx.z;
        A    += (size_t)z * 1000 * 256;
        Bm   += (size_t)z * 1000 * 256;
        C    += (size_t)z * 1000 * 1000;
        e1   += (size_t)z * 1000 * 1000;   // mask slice
        rsum += z * 1000;
    }

    float acc[8][8];
#pragma unroll
    for (int i = 0; i < 8; ++i)
#pragma unroll
        for (int j = 0; j < 8; ++j) acc[i][j] = 0.f;

    for (int k0 = 0; k0 < 256; k0 += 16) {
        // A tile: rows m0..m0+127, cols k0..k0+15, store k-major (transposed)
#pragma unroll
        for (int i = 0; i < 2; ++i) {
            int v = tid + i * 256;
            int r = v >> 2, c4 = v & 3;
            float4 av = make_float4(0.f, 0.f, 0.f, 0.f);
            if (m0 + r < M)
                av = *(const float4*)(A + (size_t)(m0 + r) * 256 + k0 + c4 * 4);
            As[(c4 * 4 + 0) * 132 + r] = av.x;
            As[(c4 * 4 + 1) * 132 + r] = av.y;
            As[(c4 * 4 + 2) * 132 + r] = av.z;
            As[(c4 * 4 + 3) * 132 + r] = av.w;
        }
        if (MODE == 3) {
            // B^T: B is [N,256] row-major; tile rows n0..n0+127 cols k0..k0+15
#pragma unroll
            for (int i = 0; i < 2; ++i) {
                int v = tid + i * 256;
                int r = v >> 2, c4 = v & 3;
                float4 bv = make_float4(0.f, 0.f, 0.f, 0.f);
                if (n0 + r < N)
                    bv = *(const float4*)(Bm + (size_t)(n0 + r) * 256 + k0 + c4 * 4);
                Bs[(c4 * 4 + 0) * 132 + r] = bv.x;
                Bs[(c4 * 4 + 1) * 132 + r] = bv.y;
                Bs[(c4 * 4 + 2) * 132 + r] = bv.z;
                Bs[(c4 * 4 + 3) * 132 + r] = bv.w;
            }
        } else {
            // NN: B is [256, 256] row-major; tile rows k0..k0+15, cols n0..n0+127
#pragma unroll
            for (int i = 0; i < 2; ++i) {
                int v = tid + i * 256;
                int kk = v >> 5, c4 = v & 31;
                float4 bv = *(const float4*)(Bm + (size_t)(k0 + kk) * 256 + n0 + c4 * 4);
                *(float4*)&Bs[kk * 132 + c4 * 4] = bv;
            }
        }
        __syncthreads();
#pragma unroll
        for (int kk = 0; kk < 16; ++kk) {
            float a[8], b[8];
            *(float4*)&a[0] = *(const float4*)&As[kk * 132 + ty * 8];
            *(float4*)&a[4] = *(const float4*)&As[kk * 132 + ty * 8 + 4];
            *(float4*)&b[0] = *(const float4*)&Bs[kk * 132 + tx * 8];
            *(float4*)&b[4] = *(const float4*)&Bs[kk * 132 + tx * 8 + 4];
#pragma unroll
            for (int i = 0; i < 8; ++i)
#pragma unroll
                for (int j = 0; j < 8; ++j)
                    acc[i][j] += a[i] * b[j];
        }
        __syncthreads();
    }

    if (MODE != 3) {
#pragma unroll
        for (int i = 0; i < 8; ++i) {
            int row = m0 + ty * 8 + i;
            if (row >= M) continue;
            float at = (MODE == 1) ? e1[row] : 0.f;
#pragma unroll
            for (int j = 0; j < 8; ++j) {
                int col = n0 + tx * 8 + j;
                float c = acc[i][j];
                if (MODE == 1) c += at * e2[col];   // attr * Wq_last[256,:]
                if (MODE == 2) c += e1[col];        // + bc
                C[(size_t)row * 256 + col] = c;
            }
        }
    } else {
        float rp[8];
#pragma unroll
        for (int i = 0; i < 8; ++i) {
            rp[i] = 0.f;
            int row = m0 + ty * 8 + i;
            if (row < M) {
#pragma unroll
                for (int j = 0; j < 8; ++j) {
                    int col = n0 + tx * 8 + j;
                    if (col < N) {
                        float x = acc[i][j];
                        float l = 10.0f * tanhf(x * 0.0625f)
                                + e1[(size_t)row * 1000 + col];
                        float e = expf(l);
                        C[(size_t)row * 1000 + col] = e;
                        rp[i] += e;
                    }
                }
            }
        }
        // block-reduce per-row partials across the 16 tx lanes, then atomicAdd
#pragma unroll
        for (int i = 0; i < 8; ++i)
            As[(ty * 8 + i) * 16 + tx] = rp[i];
        __syncthreads();
        if (tid < 128) {
            float s = 0.f;
#pragma unroll
            for (int t = 0; t < 16; ++t) s += As[tid * 16 + t];
            if (m0 + tid < M) atomicAdd(&rsum[m0 + tid], s);
        }
    }
}

// ---------------- attention: per (b,h), 64 p-rows x full N sweep ----------------
// Logits ~ N(0, 0.1): exp without max-subtraction is numerically safe.
__global__ void __launch_bounds__(256)
attn_k(const float* __restrict__ mask)
{
    __shared__ float Ks[128 * 16];
    __shared__ float Vs[128 * 16];
    __shared__ float Ms[64 * 128];  // XOR-swizzled; total static smem = 48KB exactly

    const int tid = threadIdx.x;
    const int bh = blockIdx.y;
    const int b = bh >> 4, h = bh & 15;
    const int p0 = blockIdx.x * 64;
    const int r = tid & 63;
    const int qp = tid >> 6;
    const int p = p0 + r;
    const bool prow = (p < 1000);

    float qreg[16];
    if (prow) {
        const float* qptr = g_Q + (size_t)(b * 1000 + p) * 256 + h * 16;
#pragma unroll
        for (int i = 0; i < 4; ++i)
            *(float4*)&qreg[i * 4] = *(const float4*)(qptr + i * 4);
    } else {
#pragma unroll
        for (int d = 0; d < 16; ++d) qreg[d] = 0.f;
    }

    float acc[16];
#pragma unroll
    for (int d = 0; d < 16; ++d) acc[d] = 0.f;
    float denom = 0.f;

    const float* maskb = mask + (size_t)b * 1000 * 1000;

    for (int nt = 0; nt < 1000; nt += 128) {
        // K/V tiles
#pragma unroll
        for (int i = 0; i < 2; ++i) {
            int v = tid + i * 256;
            int rr = v >> 2, c4 = v & 3;
            int n = nt + rr;
            float4 kv = make_float4(0.f, 0.f, 0.f, 0.f);
            float4 vv = make_float4(0.f, 0.f, 0.f, 0.f);
            if (n < 1000) {
                size_t off = (size_t)(b * 1000 + n) * 256 + h * 16 + c4 * 4;
                kv = *(const float4*)(g_K + off);
                vv = *(const float4*)(g_V + off);
            }
            *(float4*)&Ks[rr * 16 + c4 * 4] = kv;
            *(float4*)&Vs[rr * 16 + c4 * 4] = vv;
        }
        // mask tile [64 p-rows][128 n-cols], XOR swizzle for conflict-free reads
#pragma unroll
        for (int i = 0; i < 32; ++i) {
            int v = tid + i * 256;
            int row = v >> 7, col = v & 127;
            int pp = p0 + row, nn2 = nt + col;
            float mv = (pp < 1000 && nn2 < 1000)
                     ? maskb[(size_t)pp * 1000 + nn2] : 0.f;
            Ms[row * 128 + (col ^ (row & 31))] = mv;
        }
        __syncthreads();

        if (prow) {
#pragma unroll 4
            for (int jj = 0; jj < 32; ++jj) {
                int nl = qp * 32 + jj;           // uniform across warp
                if (nt + nl < 1000) {
                    const float* kp = &Ks[nl * 16];
                    float s = 0.f;
#pragma unroll
                    for (int d = 0; d < 16; ++d) s = fmaf(qreg[d], kp[d], s);
                    s = s * 0.25f + Ms[r * 128 + (nl ^ (r & 31))];
                    float e = expf(s);
                    denom += e;
                    const float* vp = &Vs[nl * 16];
#pragma unroll
                    for (int d = 0; d < 16; ++d) acc[d] = fmaf(e, vp[d], acc[d]);
                }
            }
        }
        __syncthreads();
    }

    // reduce the 4 n-quarters per row (reuse Ms as scratch)
    float* red = Ms;
    int base = (r * 4 + qp) * 17;
#pragma unroll
    for (int d = 0; d < 16; ++d) red[base + d] = acc[d];
    red[base + 16] = denom;
    __syncthreads();

    if (qp == 0 && prow) {
        float tot[16];
#pragma unroll
        for (int d = 0; d < 16; ++d) tot[d] = 0.f;
        float dt = 0.f;
#pragma unroll
        for (int g = 0; g < 4; ++g) {
            int bb = (r * 4 + g) * 17;
            dt += red[bb + 16];
#pragma unroll
            for (int d = 0; d < 16; ++d) tot[d] += red[bb + d];
        }
        float inv = 1.f / dt;
        float* op = g_ATT + (size_t)(b * 1000 + p) * 256 + h * 16;
#pragma unroll
        for (int d = 0; d < 16; ++d) op[d] = tot[d] * inv;
    }
}

// ---------------- normalize: probs = e / rowsum ----------------
__global__ void norm_k(float* __restrict__ out) {
    int row = blockIdx.x;
    float inv = 1.0f / g_ROWSUM[row];
    float* p = out + (size_t)row * 1000;
    for (int c = threadIdx.x; c < 1000; c += 256) p[c] *= inv;
}

// ---------------- launch ----------------
extern "C" void kernel_launch(void* const* d_in, const int* in_sizes, int n_in,
                              void* d_out, int out_size)
{
    const float* last  = (const float*)d_in[0];  // [16,1000,256]
    const float* attr  = (const float*)d_in[1];  // [16,1000,1]
    const float* mask  = (const float*)d_in[2];  // [16,1000,1000]
    const float* nodes = (const float*)d_in[3];  // [16,1000,256]
    const float* Wq    = (const float*)d_in[4];  // [257,256]
    const float* Wk    = (const float*)d_in[5];  // [256,256]
    const float* Wv    = (const float*)d_in[6];  // [256,256]
    const float* Wc    = (const float*)d_in[7];  // [256,256]
    const float* bc    = (const float*)d_in[8];  // [256]
    float* out = (float*)d_out;

    void* p;
    cudaGetSymbolAddress(&p, g_K);      float* gK   = (float*)p;
    cudaGetSymbolAddress(&p, g_V);      float* gV   = (float*)p;
    cudaGetSymbolAddress(&p, g_Q);      float* gQ   = (float*)p;
    cudaGetSymbolAddress(&p, g_ATT);    float* gATT = (float*)p;
    cudaGetSymbolAddress(&p, g_MH);     float* gMH  = (float*)p;
    cudaGetSymbolAddress(&p, g_ROWSUM); float* gRS  = (float*)p;

    zero_k<<<(MROWS + 255) / 256, 256>>>();

    dim3 gProj(2, 125);  // N=256 -> 2 tiles, M=16000 -> 125 tiles
    gemm_k<0><<<gProj, 256>>>(nodes, Wk, gK, MROWS, 256, nullptr, nullptr, nullptr);
    gemm_k<0><<<gProj, 256>>>(nodes, Wv, gV, MROWS, 256, nullptr, nullptr, nullptr);
    gemm_k<1><<<gProj, 256>>>(last, Wq, gQ, MROWS, 256, attr, Wq + 256 * 256, nullptr);

    attn_k<<<dim3(16, 256), 256>>>(mask);  // 16 p-tiles x (B*H=256)

    gemm_k<2><<<gProj, 256>>>(gATT, Wc, gMH, MROWS, 256, bc, nullptr, nullptr);

    dim3 gBig(8, 8, 16);  // 1000x1000 per batch, 16 batches
    gemm_k<3><<<gBig, 256>>>(gMH, nodes, out, 1000, 1000, mask, nullptr, gRS);

    norm_k<<<MROWS, 256>>>(out);
}

// round 2
// speedup vs baseline: 1.1991x; 1.1991x over previous
#include <cuda_runtime.h>
#include <math.h>

// B=16, P=1000, N=1000, E=256, H=16, D=16, HD=256
#define BSZ   16
#define PN    1000
#define ED    256
#define MROWS (BSZ * PN)   // 16000
#define LOG2E 1.4426950408889634f

typedef unsigned long long u64;

__device__ __forceinline__ u64 dup2(float x) {
    u64 r; asm("mov.b64 %0,{%1,%1};" : "=l"(r) : "f"(x)); return r;
}
__device__ __forceinline__ void unpack2(u64 v, float& x, float& y) {
    asm("mov.b64 {%0,%1},%2;" : "=f"(x), "=f"(y) : "l"(v));
}
__device__ __forceinline__ void ffma2(u64& d, u64 a, u64 b) {
    asm("fma.rn.f32x2 %0,%1,%2,%0;" : "+l"(d) : "l"(a), "l"(b));
}
__device__ __forceinline__ u64 fadd2(u64 a, u64 b) {
    u64 r; asm("add.rn.f32x2 %0,%1,%2;" : "=l"(r) : "l"(a), "l"(b)); return r;
}
__device__ __forceinline__ float ex2f(float x) {
    float y; asm("ex2.approx.f32 %0,%1;" : "=f"(y) : "f"(x)); return y;
}

// ---------------- scratch ----------------
__device__ float g_KV[MROWS * 512];   // cols 0..255 = K, 256..511 = V
__device__ float g_Q[MROWS * ED];
__device__ float g_ATT[MROWS * ED];
__device__ float g_MH[MROWS * ED];
__device__ float g_WKV[ED * 512];
__device__ float g_ROWSUM[MROWS];

__global__ void zero_k() {
    int i = blockIdx.x * 256 + threadIdx.x;
    if (i < MROWS) g_ROWSUM[i] = 0.f;
}

__global__ void concat_wkv(const float* __restrict__ Wk, const float* __restrict__ Wv) {
    int i = blockIdx.x * 256 + threadIdx.x;   // 256*512 total
    int k = i >> 9, j = i & 511;
    g_WKV[i] = (j < 256) ? Wk[k * 256 + j] : Wv[k * 256 + (j - 256)];
}

// ---------------- GEMM (double-buffered, fp32x2 microkernel) ----------------
// MODE 0: C = A @ B                       (A [M,256], B [256,ldb-wide])
// MODE 1: C = A @ B + attr[row]*wqrow[col]
// MODE 2: C = A @ B + bias[col]
// MODE 3: per-batch C = A @ B^T, epilogue exp(10*tanh(x/16)+mask), rowsum
template <int MODE>
__global__ void __launch_bounds__(256, 2)
gemm_k(const float* __restrict__ A, const float* __restrict__ Bm,
       float* __restrict__ C, int M, int N, int ldb, int ldc,
       const float* __restrict__ e1, const float* __restrict__ e2,
       float* __restrict__ rsum)
{
    __shared__ __align__(16) float As[2][16 * 132];
    __shared__ __align__(16) float Bs[2][16 * 132];

    const int tid = threadIdx.x;
    const int tx = tid & 15;
    const int ty = tid >> 4;
    const int m0 = blockIdx.y * 128;
    const int n0 = blockIdx.x * 128;

    if (MODE == 3) {
        const int z = blockIdx.z;
        A    += (size_t)z * 1000 * 256;
        Bm   += (size_t)z * 1000 * 256;
        C    += (size_t)z * 1000 * 1000;
        e1   += (size_t)z * 1000 * 1000;
        rsum += z * 1000;
    }

    // loader indices
    const int rA = tid >> 2;       // 0..63
    const int cA = tid & 3;        // float4 index within 16-wide k
    const int rB = tid >> 5;       // 0..7 (kk for row-major B)
    const int cB = tid & 31;       // float4 col

    const float4 f4z = make_float4(0.f, 0.f, 0.f, 0.f);
    float4 aR0, aR1, bR0, bR1;

    // acc2[j][ipair]: pairs along i (rows 2*ip, 2*ip+1)
    u64 acc2[8][4];
#pragma unroll
    for (int j = 0; j < 8; ++j)
#pragma unroll
        for (int p = 0; p < 4; ++p) acc2[j][p] = 0ULL;

#define LDA(K0) { \
    const float* ap = A + (size_t)(m0 + rA) * 256 + (K0) + cA * 4; \
    if (MODE == 3) { \
        aR0 = (m0 + rA      < M) ? *(const float4*)ap            : f4z; \
        aR1 = (m0 + rA + 64 < M) ? *(const float4*)(ap + 64*256) : f4z; \
    } else { \
        aR0 = *(const float4*)ap; \
        aR1 = *(const float4*)(ap + 64 * 256); \
    } }

#define LDB(K0) { \
    if (MODE == 3) { \
        const float* bp = Bm + (size_t)(n0 + rA) * 256 + (K0) + cA * 4; \
        bR0 = (n0 + rA      < N) ? *(const float4*)bp            : f4z; \
        bR1 = (n0 + rA + 64 < N) ? *(const float4*)(bp + 64*256) : f4z; \
    } else { \
        const float* bp = Bm + (size_t)((K0) + rB) * ldb + n0 + cB * 4; \
        bR0 = *(const float4*)bp; \
        bR1 = *(const float4*)(bp + 8 * ldb); \
    } }

#define STA(BUF) { \
    As[BUF][(cA*4+0)*132 + rA] = aR0.x; As[BUF][(cA*4+1)*132 + rA] = aR0.y; \
    As[BUF][(cA*4+2)*132 + rA] = aR0.z; As[BUF][(cA*4+3)*132 + rA] = aR0.w; \
    As[BUF][(cA*4+0)*132 + rA+64] = aR1.x; As[BUF][(cA*4+1)*132 + rA+64] = aR1.y; \
    As[BUF][(cA*4+2)*132 + rA+64] = aR1.z; As[BUF][(cA*4+3)*132 + rA+64] = aR1.w; }

#define STB(BUF) { \
    if (MODE == 3) { \
        Bs[BUF][(cA*4+0)*132 + rA] = bR0.x; Bs[BUF][(cA*4+1)*132 + rA] = bR0.y; \
        Bs[BUF][(cA*4+2)*132 + rA] = bR0.z; Bs[BUF][(cA*4+3)*132 + rA] = bR0.w; \
        Bs[BUF][(cA*4+0)*132 + rA+64] = bR1.x; Bs[BUF][(cA*4+1)*132 + rA+64] = bR1.y; \
        Bs[BUF][(cA*4+2)*132 + rA+64] = bR1.z; Bs[BUF][(cA*4+3)*132 + rA+64] = bR1.w; \
    } else { \
        *(float4*)&Bs[BUF][rB * 132 + cB * 4] = bR0; \
        *(float4*)&Bs[BUF][(rB + 8) * 132 + cB * 4] = bR1; \
    } }

    LDA(0) LDB(0)
    STA(0) STB(0)
    __syncthreads();

#pragma unroll 1
    for (int t = 0; t < 16; ++t) {
        const int buf = t & 1;
        if (t < 15) { LDA((t + 1) * 16) LDB((t + 1) * 16) }
#pragma unroll
        for (int kk = 0; kk < 16; ++kk) {
            const ulonglong2* ap = (const ulonglong2*)&As[buf][kk * 132 + ty * 8];
            ulonglong2 av0 = ap[0], av1 = ap[1];
            u64 a2[4] = {av0.x, av0.y, av1.x, av1.y};
            float4 b0 = *(const float4*)&Bs[buf][kk * 132 + tx * 8];
            float4 b1 = *(const float4*)&Bs[buf][kk * 132 + tx * 8 + 4];
            u64 bd[8];
            bd[0] = dup2(b0.x); bd[1] = dup2(b0.y); bd[2] = dup2(b0.z); bd[3] = dup2(b0.w);
            bd[4] = dup2(b1.x); bd[5] = dup2(b1.y); bd[6] = dup2(b1.z); bd[7] = dup2(b1.w);
#pragma unroll
            for (int j = 0; j < 8; ++j)
#pragma unroll
                for (int p = 0; p < 4; ++p)
                    ffma2(acc2[j][p], a2[p], bd[j]);
        }
        if (t < 15) {
            STA(buf ^ 1) STB(buf ^ 1)
            __syncthreads();
        }
    }

    const int row0 = m0 + ty * 8;
    const int col0 = n0 + tx * 8;

    if (MODE != 3) {
        float ecol[8];
        if (MODE == 1) {
#pragma unroll
            for (int j = 0; j < 8; ++j) ecol[j] = e2[col0 + j];
        }
        if (MODE == 2) {
#pragma unroll
            for (int j = 0; j < 8; ++j) ecol[j] = e1[col0 + j];
        }
#pragma unroll
        for (int p = 0; p < 4; ++p) {
            float lo[8], hi[8];
#pragma unroll
            for (int j = 0; j < 8; ++j) unpack2(acc2[j][p], lo[j], hi[j]);
            int ra = row0 + 2 * p, rb = ra + 1;
            if (MODE == 1) {
                float ea = e1[ra], eb = e1[rb];
#pragma unroll
                for (int j = 0; j < 8; ++j) { lo[j] += ea * ecol[j]; hi[j] += eb * ecol[j]; }
            }
            if (MODE == 2) {
#pragma unroll
                for (int j = 0; j < 8; ++j) { lo[j] += ecol[j]; hi[j] += ecol[j]; }
            }
            *(float4*)&C[(size_t)ra * ldc + col0]     = make_float4(lo[0], lo[1], lo[2], lo[3]);
            *(float4*)&C[(size_t)ra * ldc + col0 + 4] = make_float4(lo[4], lo[5], lo[6], lo[7]);
            *(float4*)&C[(size_t)rb * ldc + col0]     = make_float4(hi[0], hi[1], hi[2], hi[3]);
            *(float4*)&C[(size_t)rb * ldc + col0 + 4] = make_float4(hi[4], hi[5], hi[6], hi[7]);
        }
    } else {
        float rp[8];
#pragma unroll
        for (int i = 0; i < 8; ++i) rp[i] = 0.f;
        const bool colok = (col0 + 7 < N);
#pragma unroll
        for (int p = 0; p < 4; ++p) {
            float vr[2][8];
#pragma unroll
            for (int j = 0; j < 8; ++j) unpack2(acc2[j][p], vr[0][j], vr[1][j]);
#pragma unroll
            for (int h = 0; h < 2; ++h) {
                int i = 2 * p + h;
                int row = row0 + i;
                if (row >= M) continue;
                if (colok) {
                    float ev[8];
                    float s = 0.f;
#pragma unroll
                    for (int j = 0; j < 8; ++j) {
                        float l = 10.0f * tanhf(vr[h][j] * 0.0625f)
                                + e1[(size_t)row * 1000 + col0 + j];
                        float e = ex2f(l * LOG2E);
                        ev[j] = e; s += e;
                    }
                    rp[i] = s;
                    *(float4*)&C[(size_t)row * 1000 + col0]     = make_float4(ev[0], ev[1], ev[2], ev[3]);
                    *(float4*)&C[(size_t)row * 1000 + col0 + 4] = make_float4(ev[4], ev[5], ev[6], ev[7]);
                } else {
                    float s = 0.f;
#pragma unroll
                    for (int j = 0; j < 8; ++j) {
                        int col = col0 + j;
                        if (col < N) {
                            float l = 10.0f * tanhf(vr[h][j] * 0.0625f)
                                    + e1[(size_t)row * 1000 + col];
                            float e = ex2f(l * LOG2E);
                            C[(size_t)row * 1000 + col] = e;
                            s += e;
                        }
                    }
                    rp[i] = s;
                }
            }
        }
        __syncthreads();
        float* red = &As[0][0];
#pragma unroll
        for (int i = 0; i < 8; ++i)
            red[(ty * 8 + i) * 16 + tx] = rp[i];
        __syncthreads();
        if (tid < 128) {
            float s = 0.f;
#pragma unroll
            for (int t2 = 0; t2 < 16; ++t2) s += red[tid * 16 + t2];
            if (m0 + tid < M) atomicAdd(&rsum[m0 + tid], s);
        }
    }
#undef LDA
#undef LDB
#undef STA
#undef STB
}

// ---------------- attention (fp32x2, branch-free inner loop) ----------------
__global__ void __launch_bounds__(256)
attn_k(const float* __restrict__ mask)
{
    __shared__ __align__(16) float Ks[128 * 16];
    __shared__ __align__(16) float Vs[128 * 16];
    __shared__ __align__(16) float Ms[64 * 128];   // total 48KB

    const int tid = threadIdx.x;
    const int bh = blockIdx.y;
    const int b = bh >> 4, h = bh & 15;
    const int p0 = blockIdx.x * 64;
    const int r = tid & 63;
    const int qp = tid >> 6;
    const int p = p0 + r;
    const bool prow = (p < 1000);

    // q pre-scaled by 0.25 * log2(e), packed into pairs
    u64 q2[8];
    {
        float qreg[16];
        if (prow) {
            const float* qptr = g_Q + (size_t)(b * 1000 + p) * 256 + h * 16;
#pragma unroll
            for (int i = 0; i < 4; ++i)
                *(float4*)&qreg[i * 4] = *(const float4*)(qptr + i * 4);
        } else {
#pragma unroll
            for (int d = 0; d < 16; ++d) qreg[d] = 0.f;
        }
        const float sc = 0.25f * LOG2E;
#pragma unroll
        for (int d = 0; d < 16; ++d) qreg[d] *= sc;
#pragma unroll
        for (int d = 0; d < 8; ++d) {
            u64 v; asm("mov.b64 %0,{%1,%2};" : "=l"(v) : "f"(qreg[2*d]), "f"(qreg[2*d+1]));
            q2[d] = v;
        }
    }

    u64 acc2[8];
#pragma unroll
    for (int d = 0; d < 8; ++d) acc2[d] = 0ULL;
    float denom = 0.f;

    const float* maskb = mask + (size_t)b * 1000 * 1000;

    for (int nt = 0; nt < 1024; nt += 128) {
        // K/V tiles (zero-padded)
#pragma unroll
        for (int i = 0; i < 2; ++i) {
            int v = tid + i * 256;
            int rr = v >> 2, c4 = v & 3;
            int n = nt + rr;
            float4 kv = make_float4(0.f, 0.f, 0.f, 0.f);
            float4 vv = kv;
            if (n < 1000) {
                size_t off = (size_t)(b * 1000 + n) * 512 + h * 16 + c4 * 4;
                kv = *(const float4*)(g_KV + off);
                vv = *(const float4*)(g_KV + off + 256);
            }
            *(float4*)&Ks[rr * 16 + c4 * 4] = kv;
            *(float4*)&Vs[rr * 16 + c4 * 4] = vv;
        }
        // mask tile, pre-scaled by log2(e); -1e30 padding kills n >= 1000
#pragma unroll
        for (int i = 0; i < 32; ++i) {
            int v = tid + i * 256;
            int row = v >> 7, col = v & 127;
            int pp = p0 + row, nn2 = nt + col;
            float mv = (pp < 1000 && nn2 < 1000)
                     ? maskb[(size_t)pp * 1000 + nn2] * LOG2E : -1e30f;
            Ms[row * 128 + (col ^ (row & 31))] = mv;
        }
        __syncthreads();

#pragma unroll 4
        for (int jj = 0; jj < 32; ++jj) {
            int nl = qp * 32 + jj;    // uniform across warp
            const ulonglong2* kp = (const ulonglong2*)&Ks[nl * 16];
            ulonglong2 ka = kp[0], kb = kp[1];
            u64 sa = 0ULL, sb = 0ULL;
            ffma2(sa, q2[0], ka.x); ffma2(sb, q2[1], ka.y);
            ffma2(sa, q2[2], kb.x); ffma2(sb, q2[3], kb.y);
            const ulonglong2* kp2 = kp + 2;
            ulonglong2 kc = kp2[0], kd = kp2[1];
            ffma2(sa, q2[4], kc.x); ffma2(sb, q2[5], kc.y);
            ffma2(sa, q2[6], kd.x); ffma2(sb, q2[7], kd.y);
            u64 st = fadd2(sa, sb);
            float slo, shi; unpack2(st, slo, shi);
            float s = slo + shi + Ms[r * 128 + (nl ^ (r & 31))];
            float e = ex2f(s);
            denom += e;
            u64 ed = dup2(e);
            const ulonglong2* vp = (const ulonglong2*)&Vs[nl * 16];
            ulonglong2 va = vp[0], vb = vp[1], vc = vp[2], vd = vp[3];
            ffma2(acc2[0], ed, va.x); ffma2(acc2[1], ed, va.y);
            ffma2(acc2[2], ed, vb.x); ffma2(acc2[3], ed, vb.y);
            ffma2(acc2[4], ed, vc.x); ffma2(acc2[5], ed, vc.y);
            ffma2(acc2[6], ed, vd.x); ffma2(acc2[7], ed, vd.y);
        }
        __syncthreads();
    }

    // reduce the 4 n-quarters per row (reuse Ms)
    float* red = Ms;
    int base = (r * 4 + qp) * 17;
#pragma unroll
    for (int d = 0; d < 8; ++d)
        unpack2(acc2[d], red[base + 2 * d], red[base + 2 * d + 1]);
    red[base + 16] = denom;
    __syncthreads();

    if (qp == 0 && prow) {
        float tot[16];
#pragma unroll
        for (int d = 0; d < 16; ++d) tot[d] = 0.f;
        float dt = 0.f;
#pragma unroll
        for (int g = 0; g < 4; ++g) {
            int bb = (r * 4 + g) * 17;
            dt += red[bb + 16];
#pragma unroll
            for (int d = 0; d < 16; ++d) tot[d] += red[bb + d];
        }
        float inv = 1.f / dt;
        float* op = g_ATT + (size_t)(b * 1000 + p) * 256 + h * 16;
#pragma unroll
        for (int d = 0; d < 16; ++d) op[d] = tot[d] * inv;
    }
}

// ---------------- normalize ----------------
__global__ void norm_k(float* __restrict__ out) {
    int row = blockIdx.x;
    int c = threadIdx.x;
    if (c < 250) {
        float inv = 1.0f / g_ROWSUM[row];
        float4* p = (float4*)(out + (size_t)row * 1000);
        float4 v = p[c];
        v.x *= inv; v.y *= inv; v.z *= inv; v.w *= inv;
        p[c] = v;
    }
}

// ---------------- launch ----------------
extern "C" void kernel_launch(void* const* d_in, const int* in_sizes, int n_in,
                              void* d_out, int out_size)
{
    const float* last  = (const float*)d_in[0];  // [16,1000,256]
    const float* attr  = (const float*)d_in[1];  // [16,1000,1]
    const float* mask  = (const float*)d_in[2];  // [16,1000,1000]
    const float* nodes = (const float*)d_in[3];  // [16,1000,256]
    const float* Wq    = (const float*)d_in[4];  // [257,256]
    const float* Wk    = (const float*)d_in[5];  // [256,256]
    const float* Wv    = (const float*)d_in[6];  // [256,256]
    const float* Wc    = (const float*)d_in[7];  // [256,256]
    const float* bc    = (const float*)d_in[8];  // [256]
    float* out = (float*)d_out;

    void* p;
    cudaGetSymbolAddress(&p, g_KV);     float* gKV  = (float*)p;
    cudaGetSymbolAddress(&p, g_Q);      float* gQ   = (float*)p;
    cudaGetSymbolAddress(&p, g_ATT);    float* gATT = (float*)p;
    cudaGetSymbolAddress(&p, g_MH);     float* gMH  = (float*)p;
    cudaGetSymbolAddress(&p, g_WKV);    float* gWKV = (float*)p;
    cudaGetSymbolAddress(&p, g_ROWSUM); float* gRS  = (float*)p;

    zero_k<<<(MROWS + 255) / 256, 256>>>();
    concat_wkv<<<512, 256>>>(Wk, Wv);

    // fused K|V projection: [16000,256] @ [256,512]
    gemm_k<0><<<dim3(4, 125), 256>>>(nodes, gWKV, gKV, MROWS, 512, 512, 512,
                                     nullptr, nullptr, nullptr);
    // Q projection with attr concat term
    gemm_k<1><<<dim3(2, 125), 256>>>(last, Wq, gQ, MROWS, 256, 256, 256,
                                     attr, Wq + 256 * 256, nullptr);

    attn_k<<<dim3(16, 256), 256>>>(mask);

    // Wc projection + bias
    gemm_k<2><<<dim3(2, 125), 256>>>(gATT, Wc, gMH, MROWS, 256, 256, 256,
                                     bc, nullptr, nullptr);

    // probe GEMM + clipped-softmax epilogue
    gemm_k<3><<<dim3(8, 8, 16), 256>>>(gMH, nodes, out, 1000, 1000, 256, 1000,
                                       mask, nullptr, gRS);

    norm_k<<<MROWS, 256>>>(out);
}

// round 3
// speedup vs baseline: 1.2875x; 1.0737x over previous
#include <cuda_runtime.h>
#include <math.h>

// B=16, P=1000, N=1000, E=256, H=16, D=16, HD=256
#define BSZ   16
#define PN    1000
#define ED    256
#define MROWS (BSZ * PN)   // 16000
#define LOG2E 1.4426950408889634f

typedef unsigned long long u64;

__device__ __forceinline__ u64 dup2(float x) {
    u64 r; asm("mov.b64 %0,{%1,%1};" : "=l"(r) : "f"(x)); return r;
}
__device__ __forceinline__ void unpack2(u64 v, float& x, float& y) {
    asm("mov.b64 {%0,%1},%2;" : "=f"(x), "=f"(y) : "l"(v));
}
__device__ __forceinline__ void ffma2(u64& d, u64 a, u64 b) {
    asm("fma.rn.f32x2 %0,%1,%2,%0;" : "+l"(d) : "l"(a), "l"(b));
}
__device__ __forceinline__ u64 fadd2(u64 a, u64 b) {
    u64 r; asm("add.rn.f32x2 %0,%1,%2;" : "=l"(r) : "l"(a), "l"(b)); return r;
}
__device__ __forceinline__ float ex2f(float x) {
    float y; asm("ex2.approx.f32 %0,%1;" : "=f"(y) : "f"(x)); return y;
}
__device__ __forceinline__ float frcp(float x) {
    float y; asm("rcp.approx.f32 %0,%1;" : "=f"(y) : "f"(x)); return y;
}

// ---------------- scratch ----------------
__device__ float g_KV[MROWS * 512];   // cols 0..255 = K, 256..511 = V
__device__ float g_Q[MROWS * ED];
__device__ float g_ATT[MROWS * ED];
__device__ float g_MH[MROWS * ED];
__device__ float g_WKV[ED * 512];
__device__ float g_ROWSUM[MROWS];

__global__ void zero_k() {
    int i = blockIdx.x * 256 + threadIdx.x;
    if (i < MROWS) g_ROWSUM[i] = 0.f;
}

__global__ void concat_wkv(const float* __restrict__ Wk, const float* __restrict__ Wv) {
    int i = blockIdx.x * 256 + threadIdx.x;   // 256*512 total
    int k = i >> 9, j = i & 511;
    g_WKV[i] = (j < 256) ? Wk[k * 256 + j] : Wv[k * 256 + (j - 256)];
}

// ---------------- GEMM (double-buffered, fp32x2 microkernel) ----------------
// MODE 0: C = A @ B
// MODE 1: C = A @ B + attr[row]*wqrow[col]
// MODE 2: C = A @ B + bias[col]
// MODE 3: per-batch C = A @ B^T, epilogue exp(10*tanh(x/16)+mask), rowsum
template <int MODE>
__global__ void __launch_bounds__(256, 2)
gemm_k(const float* __restrict__ A, const float* __restrict__ Bm,
       float* __restrict__ C, int M, int N, int ldb, int ldc,
       const float* __restrict__ e1, const float* __restrict__ e2,
       float* __restrict__ rsum)
{
    __shared__ __align__(16) float As[2][16 * 132];
    __shared__ __align__(16) float Bs[2][16 * 132];

    const int tid = threadIdx.x;
    const int tx = tid & 15;
    const int ty = tid >> 4;
    const int m0 = blockIdx.y * 128;
    const int n0 = blockIdx.x * 128;

    if (MODE == 3) {
        const int z = blockIdx.z;
        A    += (size_t)z * 1000 * 256;
        Bm   += (size_t)z * 1000 * 256;
        C    += (size_t)z * 1000 * 1000;
        e1   += (size_t)z * 1000 * 1000;
        rsum += z * 1000;
    }

    const int rA = tid >> 2;
    const int cA = tid & 3;
    const int rB = tid >> 5;
    const int cB = tid & 31;

    const float4 f4z = make_float4(0.f, 0.f, 0.f, 0.f);
    float4 aR0, aR1, bR0, bR1;

    u64 acc2[8][4];
#pragma unroll
    for (int j = 0; j < 8; ++j)
#pragma unroll
        for (int p = 0; p < 4; ++p) acc2[j][p] = 0ULL;

#define LDA(K0) { \
    const float* ap = A + (size_t)(m0 + rA) * 256 + (K0) + cA * 4; \
    if (MODE == 3) { \
        aR0 = (m0 + rA      < M) ? *(const float4*)ap            : f4z; \
        aR1 = (m0 + rA + 64 < M) ? *(const float4*)(ap + 64*256) : f4z; \
    } else { \
        aR0 = *(const float4*)ap; \
        aR1 = *(const float4*)(ap + 64 * 256); \
    } }

#define LDB(K0) { \
    if (MODE == 3) { \
        const float* bp = Bm + (size_t)(n0 + rA) * 256 + (K0) + cA * 4; \
        bR0 = (n0 + rA      < N) ? *(const float4*)bp            : f4z; \
        bR1 = (n0 + rA + 64 < N) ? *(const float4*)(bp + 64*256) : f4z; \
    } else { \
        const float* bp = Bm + (size_t)((K0) + rB) * ldb + n0 + cB * 4; \
        bR0 = *(const float4*)bp; \
        bR1 = *(const float4*)(bp + 8 * ldb); \
    } }

#define STA(BUF) { \
    As[BUF][(cA*4+0)*132 + rA] = aR0.x; As[BUF][(cA*4+1)*132 + rA] = aR0.y; \
    As[BUF][(cA*4+2)*132 + rA] = aR0.z; As[BUF][(cA*4+3)*132 + rA] = aR0.w; \
    As[BUF][(cA*4+0)*132 + rA+64] = aR1.x; As[BUF][(cA*4+1)*132 + rA+64] = aR1.y; \
    As[BUF][(cA*4+2)*132 + rA+64] = aR1.z; As[BUF][(cA*4+3)*132 + rA+64] = aR1.w; }

#define STB(BUF) { \
    if (MODE == 3) { \
        Bs[BUF][(cA*4+0)*132 + rA] = bR0.x; Bs[BUF][(cA*4+1)*132 + rA] = bR0.y; \
        Bs[BUF][(cA*4+2)*132 + rA] = bR0.z; Bs[BUF][(cA*4+3)*132 + rA] = bR0.w; \
        Bs[BUF][(cA*4+0)*132 + rA+64] = bR1.x; Bs[BUF][(cA*4+1)*132 + rA+64] = bR1.y; \
        Bs[BUF][(cA*4+2)*132 + rA+64] = bR1.z; Bs[BUF][(cA*4+3)*132 + rA+64] = bR1.w; \
    } else { \
        *(float4*)&Bs[BUF][rB * 132 + cB * 4] = bR0; \
        *(float4*)&Bs[BUF][(rB + 8) * 132 + cB * 4] = bR1; \
    } }

    LDA(0) LDB(0)
    STA(0) STB(0)
    __syncthreads();

#pragma unroll 1
    for (int t = 0; t < 16; ++t) {
        const int buf = t & 1;
        if (t < 15) { LDA((t + 1) * 16) LDB((t + 1) * 16) }
#pragma unroll
        for (int kk = 0; kk < 16; ++kk) {
            const ulonglong2* ap = (const ulonglong2*)&As[buf][kk * 132 + ty * 8];
            ulonglong2 av0 = ap[0], av1 = ap[1];
            u64 a2[4] = {av0.x, av0.y, av1.x, av1.y};
            float4 b0 = *(const float4*)&Bs[buf][kk * 132 + tx * 8];
            float4 b1 = *(const float4*)&Bs[buf][kk * 132 + tx * 8 + 4];
            u64 bd[8];
            bd[0] = dup2(b0.x); bd[1] = dup2(b0.y); bd[2] = dup2(b0.z); bd[3] = dup2(b0.w);
            bd[4] = dup2(b1.x); bd[5] = dup2(b1.y); bd[6] = dup2(b1.z); bd[7] = dup2(b1.w);
#pragma unroll
            for (int j = 0; j < 8; ++j)
#pragma unroll
                for (int p = 0; p < 4; ++p)
                    ffma2(acc2[j][p], a2[p], bd[j]);
        }
        if (t < 15) {
            STA(buf ^ 1) STB(buf ^ 1)
            __syncthreads();
        }
    }

    const int row0 = m0 + ty * 8;
    const int col0 = n0 + tx * 8;

    if (MODE != 3) {
        float ecol[8];
        if (MODE == 1) {
#pragma unroll
            for (int j = 0; j < 8; ++j) ecol[j] = e2[col0 + j];
        }
        if (MODE == 2) {
#pragma unroll
            for (int j = 0; j < 8; ++j) ecol[j] = e1[col0 + j];
        }
#pragma unroll
        for (int p = 0; p < 4; ++p) {
            float lo[8], hi[8];
#pragma unroll
            for (int j = 0; j < 8; ++j) unpack2(acc2[j][p], lo[j], hi[j]);
            int ra = row0 + 2 * p, rb = ra + 1;
            if (MODE == 1) {
                float ea = e1[ra], eb = e1[rb];
#pragma unroll
                for (int j = 0; j < 8; ++j) { lo[j] += ea * ecol[j]; hi[j] += eb * ecol[j]; }
            }
            if (MODE == 2) {
#pragma unroll
                for (int j = 0; j < 8; ++j) { lo[j] += ecol[j]; hi[j] += ecol[j]; }
            }
            *(float4*)&C[(size_t)ra * ldc + col0]     = make_float4(lo[0], lo[1], lo[2], lo[3]);
            *(float4*)&C[(size_t)ra * ldc + col0 + 4] = make_float4(lo[4], lo[5], lo[6], lo[7]);
            *(float4*)&C[(size_t)rb * ldc + col0]     = make_float4(hi[0], hi[1], hi[2], hi[3]);
            *(float4*)&C[(size_t)rb * ldc + col0 + 4] = make_float4(hi[4], hi[5], hi[6], hi[7]);
        }
    } else {
        float rp[8];
#pragma unroll
        for (int i = 0; i < 8; ++i) rp[i] = 0.f;
        const bool colok = (col0 + 7 < N);
        // tanh(x/16) = 1 - 2/(exp(x/8)+1);  logit*log2e for ex2
#pragma unroll
        for (int p = 0; p < 4; ++p) {
            float vr[2][8];
#pragma unroll
            for (int j = 0; j < 8; ++j) unpack2(acc2[j][p], vr[0][j], vr[1][j]);
#pragma unroll
            for (int h = 0; h < 2; ++h) {
                int i = 2 * p + h;
                int row = row0 + i;
                if (row >= M) continue;
                if (colok) {
                    float ev[8];
                    float s = 0.f;
#pragma unroll
                    for (int j = 0; j < 8; ++j) {
                        float z = ex2f(vr[h][j] * (0.125f * LOG2E));
                        float th = 10.f - 20.f * frcp(z + 1.f);
                        float l = th + e1[(size_t)row * 1000 + col0 + j];
                        float e = ex2f(l * LOG2E);
                        ev[j] = e; s += e;
                    }
                    rp[i] = s;
                    *(float4*)&C[(size_t)row * 1000 + col0]     = make_float4(ev[0], ev[1], ev[2], ev[3]);
                    *(float4*)&C[(size_t)row * 1000 + col0 + 4] = make_float4(ev[4], ev[5], ev[6], ev[7]);
                } else {
                    float s = 0.f;
#pragma unroll
                    for (int j = 0; j < 8; ++j) {
                        int col = col0 + j;
                        if (col < N) {
                            float z = ex2f(vr[h][j] * (0.125f * LOG2E));
                            float th = 10.f - 20.f * frcp(z + 1.f);
                            float l = th + e1[(size_t)row * 1000 + col];
                            float e = ex2f(l * LOG2E);
                            C[(size_t)row * 1000 + col] = e;
                            s += e;
                        }
                    }
                    rp[i] = s;
                }
            }
        }
        __syncthreads();
        float* red = &As[0][0];
#pragma unroll
        for (int i = 0; i < 8; ++i)
            red[(ty * 8 + i) * 16 + tx] = rp[i];
        __syncthreads();
        if (tid < 128) {
            float s = 0.f;
#pragma unroll
            for (int t2 = 0; t2 < 16; ++t2) s += red[tid * 16 + t2];
            if (m0 + tid < M) atomicAdd(&rsum[m0 + tid], s);
        }
    }
#undef LDA
#undef LDB
#undef STA
#undef STB
}

// ---------------- attention: p-tile 128, 2 p per thread, vector mask ----------------
// dyn smem: Ks[128*16] | Vs[128*16] | Ms[128*132]  = 20992 floats = 82 KB
#define ATTN_SMEM_BYTES ((2048 * 2 + 128 * 132) * 4)

__global__ void __launch_bounds__(256, 2)
attn_k(const float* __restrict__ mask)
{
    extern __shared__ __align__(16) float sm[];
    float* Ks = sm;             // 2048
    float* Vs = sm + 2048;      // 2048
    float* Ms = sm + 4096;      // 128*132

    const int tid = threadIdx.x;
    const int bh = blockIdx.y;
    const int b = bh >> 4, h = bh & 15;
    const int p0 = blockIdx.x * 128;
    const int rr = tid & 63;
    const int qp = tid >> 6;
    const int pa = p0 + rr;
    const int pb = pa + 64;
    const bool oka = (pa < 1000), okb = (pb < 1000);

    // q for both p rows, pre-scaled by 0.25*log2e, packed into d-pairs
    u64 q2a[8], q2b[8];
    {
        const float sc = 0.25f * LOG2E;
        float qa[16], qb[16];
#pragma unroll
        for (int i = 0; i < 4; ++i) {
            float4 va = oka ? *(const float4*)(g_Q + (size_t)(b * 1000 + pa) * 256 + h * 16 + i * 4) : make_float4(0,0,0,0);
            float4 vb = okb ? *(const float4*)(g_Q + (size_t)(b * 1000 + pb) * 256 + h * 16 + i * 4) : make_float4(0,0,0,0);
            qa[i*4+0]=va.x*sc; qa[i*4+1]=va.y*sc; qa[i*4+2]=va.z*sc; qa[i*4+3]=va.w*sc;
            qb[i*4+0]=vb.x*sc; qb[i*4+1]=vb.y*sc; qb[i*4+2]=vb.z*sc; qb[i*4+3]=vb.w*sc;
        }
#pragma unroll
        for (int d = 0; d < 8; ++d) {
            u64 v; asm("mov.b64 %0,{%1,%2};" : "=l"(v) : "f"(qa[2*d]), "f"(qa[2*d+1])); q2a[d] = v;
            asm("mov.b64 %0,{%1,%2};" : "=l"(v) : "f"(qb[2*d]), "f"(qb[2*d+1])); q2b[d] = v;
        }
    }

    u64 acca[8], accb[8];
#pragma unroll
    for (int d = 0; d < 8; ++d) { acca[d] = 0ULL; accb[d] = 0ULL; }
    float dena = 0.f, denb = 0.f;

    const float* maskb = mask + (size_t)b * 1000 * 1000;
    const int w = tid >> 5, l = tid & 31;

#pragma unroll 1
    for (int nt = 0; nt < 1024; nt += 128) {
        __syncthreads();
        // ---- K/V tiles: thread loads 8 floats of one row ----
        {
            int krow = tid >> 1, kc = (tid & 1) * 8;
            int n = nt + krow;
            float4 k0, k1, v0, v1;
            k0 = k1 = v0 = v1 = make_float4(0.f, 0.f, 0.f, 0.f);
            if (n < 1000) {
                const float* base = g_KV + (size_t)(b * 1000 + n) * 512 + h * 16 + kc;
                k0 = *(const float4*)base;       k1 = *(const float4*)(base + 4);
                v0 = *(const float4*)(base+256); v1 = *(const float4*)(base + 260);
            }
            *(float4*)&Ks[krow * 16 + kc]     = k0;
            *(float4*)&Ks[krow * 16 + kc + 4] = k1;
            *(float4*)&Vs[krow * 16 + kc]     = v0;
            *(float4*)&Vs[krow * 16 + kc + 4] = v1;
        }
        // ---- mask tile: warp sweeps full rows (coalesced), stride-132 pad ----
#pragma unroll
        for (int it = 0; it < 16; ++it) {
            int row = w + it * 8;
            int pp = p0 + row, c0 = l * 4, nn = nt + c0;
            float4 mv;
            if (pp < 1000 && nn + 3 < 1000) {
                mv = *(const float4*)(maskb + (size_t)pp * 1000 + nn);
                mv.x *= LOG2E; mv.y *= LOG2E; mv.z *= LOG2E; mv.w *= LOG2E;
            } else {
                mv.x = (pp < 1000 && nn     < 1000) ? maskb[(size_t)pp*1000 + nn]   * LOG2E : -1e30f;
                mv.y = (pp < 1000 && nn + 1 < 1000) ? maskb[(size_t)pp*1000 + nn+1] * LOG2E : -1e30f;
                mv.z = (pp < 1000 && nn + 2 < 1000) ? maskb[(size_t)pp*1000 + nn+2] * LOG2E : -1e30f;
                mv.w = (pp < 1000 && nn + 3 < 1000) ? maskb[(size_t)pp*1000 + nn+3] * LOG2E : -1e30f;
            }
            *(float4*)&Ms[row * 132 + c0] = mv;
        }
        __syncthreads();

        const float* msa = &Ms[rr * 132 + qp * 32];
        const float* msb = msa + 64 * 132;
#pragma unroll 2
        for (int j4 = 0; j4 < 8; ++j4) {
            float4 ma4 = *(const float4*)(msa + j4 * 4);
            float4 mb4 = *(const float4*)(msb + j4 * 4);
            float mav[4] = {ma4.x, ma4.y, ma4.z, ma4.w};
            float mbv[4] = {mb4.x, mb4.y, mb4.z, mb4.w};
#pragma unroll
            for (int u = 0; u < 4; ++u) {
                const int nl = qp * 32 + j4 * 4 + u;
                const ulonglong2* kp = (const ulonglong2*)&Ks[nl * 16];
                ulonglong2 kA = kp[0], kB = kp[1], kC = kp[2], kD = kp[3];
                u64 s0 = 0ULL, s1 = 0ULL, t0 = 0ULL, t1 = 0ULL;
                ffma2(s0, q2a[0], kA.x); ffma2(s1, q2a[1], kA.y);
                ffma2(t0, q2b[0], kA.x); ffma2(t1, q2b[1], kA.y);
                ffma2(s0, q2a[2], kB.x); ffma2(s1, q2a[3], kB.y);
                ffma2(t0, q2b[2], kB.x); ffma2(t1, q2b[3], kB.y);
                ffma2(s0, q2a[4], kC.x); ffma2(s1, q2a[5], kC.y);
                ffma2(t0, q2b[4], kC.x); ffma2(t1, q2b[5], kC.y);
                ffma2(s0, q2a[6], kD.x); ffma2(s1, q2a[7], kD.y);
                ffma2(t0, q2b[6], kD.x); ffma2(t1, q2b[7], kD.y);
                u64 ss = fadd2(s0, s1), tt = fadd2(t0, t1);
                float x0, x1, y0, y1;
                unpack2(ss, x0, x1); unpack2(tt, y0, y1);
                float ea = ex2f(x0 + x1 + mav[u]);
                float eb = ex2f(y0 + y1 + mbv[u]);
                dena += ea; denb += eb;
                u64 da = dup2(ea), db = dup2(eb);
                const ulonglong2* vp = (const ulonglong2*)&Vs[nl * 16];
                ulonglong2 vA = vp[0], vB = vp[1], vC = vp[2], vD = vp[3];
                ffma2(acca[0], da, vA.x); ffma2(acca[1], da, vA.y);
                ffma2(accb[0], db, vA.x); ffma2(accb[1], db, vA.y);
                ffma2(acca[2], da, vB.x); ffma2(acca[3], da, vB.y);
                ffma2(accb[2], db, vB.x); ffma2(accb[3], db, vB.y);
                ffma2(acca[4], da, vC.x); ffma2(acca[5], da, vC.y);
                ffma2(accb[4], db, vC.x); ffma2(accb[5], db, vC.y);
                ffma2(acca[6], da, vD.x); ffma2(acca[7], da, vD.y);
                ffma2(accb[6], db, vD.x); ffma2(accb[7], db, vD.y);
            }
        }
    }

    // ---- reduce 4 n-quarters per p-row (reuse Ms as scratch: 128*68 floats) ----
    __syncthreads();
    {
        int basea = rr * 68 + qp * 17;
        int baseb = (rr + 64) * 68 + qp * 17;
#pragma unroll
        for (int d = 0; d < 8; ++d) {
            unpack2(acca[d], Ms[basea + 2*d], Ms[basea + 2*d + 1]);
            unpack2(accb[d], Ms[baseb + 2*d], Ms[baseb + 2*d + 1]);
        }
        Ms[basea + 16] = dena;
        Ms[baseb + 16] = denb;
    }
    __syncthreads();

    if (qp == 0) {
#pragma unroll
        for (int half = 0; half < 2; ++half) {
            int p = p0 + rr + half * 64;
            if (p < 1000) {
                int rbase = (rr + half * 64) * 68;
                float tot[16];
#pragma unroll
                for (int d = 0; d < 16; ++d) tot[d] = 0.f;
                float dt = 0.f;
#pragma unroll
                for (int g = 0; g < 4; ++g) {
                    const float* rp = &Ms[rbase + g * 17];
                    dt += rp[16];
#pragma unroll
                    for (int d = 0; d < 16; ++d) tot[d] += rp[d];
                }
                float inv = 1.f / dt;
                float* op = g_ATT + (size_t)(b * 1000 + p) * 256 + h * 16;
#pragma unroll
                for (int d = 0; d < 16; ++d) op[d] = tot[d] * inv;
            }
        }
    }
}

// ---------------- normalize ----------------
__global__ void norm_k(float* __restrict__ out) {
    int row = blockIdx.x;
    int c = threadIdx.x;
    if (c < 250) {
        float inv = 1.0f / g_ROWSUM[row];
        float4* p = (float4*)(out + (size_t)row * 1000);
        float4 v = p[c];
        v.x *= inv; v.y *= inv; v.z *= inv; v.w *= inv;
        p[c] = v;
    }
}

// ---------------- launch ----------------
extern "C" void kernel_launch(void* const* d_in, const int* in_sizes, int n_in,
                              void* d_out, int out_size)
{
    const float* last  = (const float*)d_in[0];
    const float* attr  = (const float*)d_in[1];
    const float* mask  = (const float*)d_in[2];
    const float* nodes = (const float*)d_in[3];
    const float* Wq    = (const float*)d_in[4];
    const float* Wk    = (const float*)d_in[5];
    const float* Wv    = (const float*)d_in[6];
    const float* Wc    = (const float*)d_in[7];
    const float* bc    = (const float*)d_in[8];
    float* out = (float*)d_out;

    void* p;
    cudaGetSymbolAddress(&p, g_KV);     float* gKV  = (float*)p;
    cudaGetSymbolAddress(&p, g_Q);      float* gQ   = (float*)p;
    cudaGetSymbolAddress(&p, g_ATT);    float* gATT = (float*)p;
    cudaGetSymbolAddress(&p, g_MH);     float* gMH  = (float*)p;
    cudaGetSymbolAddress(&p, g_WKV);    float* gWKV = (float*)p;
    cudaGetSymbolAddress(&p, g_ROWSUM); float* gRS  = (float*)p;

    cudaFuncSetAttribute(attn_k, cudaFuncAttributeMaxDynamicSharedMemorySize,
                         ATTN_SMEM_BYTES);

    zero_k<<<(MROWS + 255) / 256, 256>>>();
    concat_wkv<<<512, 256>>>(Wk, Wv);

    gemm_k<0><<<dim3(4, 125), 256>>>(nodes, gWKV, gKV, MROWS, 512, 512, 512,
                                     nullptr, nullptr, nullptr);
    gemm_k<1><<<dim3(2, 125), 256>>>(last, Wq, gQ, MROWS, 256, 256, 256,
                                     attr, Wq + 256 * 256, nullptr);

    attn_k<<<dim3(8, 256), 256, ATTN_SMEM_BYTES>>>(mask);

    gemm_k<2><<<dim3(2, 125), 256>>>(gATT, Wc, gMH, MROWS, 256, 256, 256,
                                     bc, nullptr, nullptr);

    gemm_k<3><<<dim3(8, 8, 16), 256>>>(gMH, nodes, out, 1000, 1000, 256, 1000,
                                       mask, nullptr, gRS);

    norm_k<<<MROWS, 256>>>(out);
}